// round 4
// baseline (speedup 1.0000x reference)
#include <cuda_runtime.h>

// ---------------------------------------------------------------------------
// TensoRF slim renderer, v4.
//  prep: combined 128B texels  g_tex[i][HW][32ch] (ch0-7 density w/ basis
//        weights folded into the line texture, ch8-31 appearance).
//  render (block=ray, 256 thr):
//    Setup: per-point sampling offsets/weights (byte offsets) -> smem.
//    Pass A: sigma. 4 pts/warp, lane = pt*8+ch. Corner loads cover 4 lines
//            per instruction -> 6 wavefronts/pt.
//    Phase B: alpha (-expm1) + smem product scan -> weights.
//    Pass C: appearance. lane = channel (24 active), 1 pt/iter. Each corner
//            load touches exactly ONE 128B line -> 18 wavefronts/pt.
//            Per-lane weighted feature accumulation; basis matvec once/ray.
// ---------------------------------------------------------------------------

#define MAXG  320
#define MAXHW (MAXG * MAXG)

__device__ float4 g_tex[3ull * MAXHW * 8];   // [i][p][8 float4] texel = 128B
__device__ float4 g_ltex[3 * MAXG * 8];      // [i][g][8 float4]

// ---------------- prep: interleave channels into 128B texels ----------------
__global__ void prep_kernel(const float* __restrict__ dp, const float* __restrict__ ap,
                            const float* __restrict__ dl, const float* __restrict__ al,
                            const float* __restrict__ denw, int G) {
    __shared__ float tile[32][129];
    int HW  = G * G;
    int ntp = (HW + 127) >> 7;
    int ntl = (G + 127) >> 7;
    int b = blockIdx.x;
    if (b < 3 * ntp) {
        int i = b / ntp, t = b - i * ntp;
        int p0 = t << 7;
        int np = min(128, HW - p0);
        for (int idx = threadIdx.x; idx < 32 * 128; idx += blockDim.x) {
            int ch = idx >> 7, p = idx & 127;
            float v = 0.f;
            if (p < np)
                v = (ch < 8) ? dp[(size_t)(i * 8 + ch) * HW + p0 + p]
                             : ap[(size_t)(i * 24 + ch - 8) * HW + p0 + p];
            tile[ch][p] = v;
        }
        __syncthreads();
        float* dst = (float*)(g_tex + ((size_t)i * MAXHW + p0) * 8);
        for (int idx = threadIdx.x; idx < np * 32; idx += blockDim.x) {
            int p = idx >> 5, ch = idx & 31;
            dst[idx] = tile[ch][p];
        }
    } else {
        b -= 3 * ntp;
        int i = b / ntl, t = b - i * ntl;
        int g0 = t << 7;
        int ng = min(128, G - g0);
        for (int idx = threadIdx.x; idx < 32 * 128; idx += blockDim.x) {
            int ch = idx >> 7, g = idx & 127;
            float v = 0.f;
            if (g < ng) {
                if (ch < 8) v = dl[(i * 8 + ch) * G + g0 + g] * denw[i * 8 + ch];
                else        v = al[(i * 24 + ch - 8) * G + g0 + g];
            }
            tile[ch][g] = v;
        }
        __syncthreads();
        float* dst = (float*)(g_ltex + ((size_t)i * MAXG + g0) * 8);
        for (int idx = threadIdx.x; idx < ng * 32; idx += blockDim.x) {
            int g = idx >> 5, ch = idx & 31;
            dst[idx] = tile[ch][g];
        }
    }
}

// ---------------- render ----------------
struct S1D { int i0, i1; float w; };

__device__ __forceinline__ S1D samp1d(float c, int G) {
    float f  = (c + 1.0f) * 0.5f * (float)(G - 1);
    float ff = floorf(f);
    S1D r;
    r.w = f - ff;                 // frac from UNclipped floor (matches ref)
    int i0 = (int)ff;
    i0 = min(max(i0, 0), G - 1);
    r.i0 = i0;
    r.i1 = min(i0 + 1, G - 1);
    return r;
}

__global__ __launch_bounds__(256)
void render_kernel(const float* __restrict__ xyz,
                   const float* __restrict__ zvals,
                   const float* __restrict__ appw,
                   const float* __restrict__ aabb,
                   float* __restrict__ out,
                   int Ns, int G) {
    __shared__ float4 s_set[256 * 9];   // per-pt per-plane: offsets + weights (36KB)
    __shared__ float  s_z[256];
    __shared__ float  s_sig[256];
    __shared__ float  s_A[256];
    __shared__ float  s_B[256];
    __shared__ float  s_w[256];
    __shared__ float  s_appw[216];
    __shared__ float  s_F[96];

    const int r    = blockIdx.x;
    const int tid  = threadIdx.x;
    const int lane = tid & 31;
    const int wrp  = tid >> 5;

    for (int l = tid; l < 216; l += 256) s_appw[l] = appw[l];

    // ---------- setup: per-point sampling data ----------
    {
        size_t base = ((size_t)r * Ns + tid) * 3;
        float nc[3];
#pragma unroll
        for (int k = 0; k < 3; k++) {
            float lo = aabb[k], hi = aabb[3 + k];
            nc[k] = (xyz[base + k] - lo) * (2.0f / (hi - lo)) - 1.0f;
        }
        s_z[tid] = zvals[(size_t)r * Ns + tid];

        const int MA[3] = {0, 0, 1}, MB[3] = {1, 2, 2}, MV[3] = {2, 1, 0};
#pragma unroll
        for (int i = 0; i < 3; i++) {
            S1D sx = samp1d(nc[MA[i]], G);
            S1D sy = samp1d(nc[MB[i]], G);
            S1D st = samp1d(nc[MV[i]], G);
            int b00 = (sy.i0 * G + sx.i0) * 128;      // byte offsets (texel=128B)
            int dx  = (sx.i1 - sx.i0) * 128;
            int dy  = (sy.i1 - sy.i0) * G * 128;
            int t0  = st.i0 * 128;
            int dt  = (st.i1 - st.i0) * 128;
            s_set[tid * 9 + i * 3 + 0] = make_float4(
                __int_as_float(b00), __int_as_float(dx),
                __int_as_float(dy),  __int_as_float(t0));
            s_set[tid * 9 + i * 3 + 1] = make_float4(
                (1.f - sx.w) * (1.f - sy.w), sx.w * (1.f - sy.w),
                (1.f - sx.w) * sy.w,         sx.w * sy.w);
            s_set[tid * 9 + i * 3 + 2] = make_float4(
                1.f - st.w, st.w, __int_as_float(dt), 0.f);
        }
    }
    __syncthreads();

    // ---------- Pass A: sigma (4 pts/warp, lane = pt*8 + ch) ----------
    {
        const int t  = lane >> 3;
        const int ch = lane & 7;
        const char* tb0 = (const char*)g_tex  + (size_t)ch * 4;
        const char* lb0 = (const char*)g_ltex + (size_t)ch * 4;
        for (int it = 0; it < 8; it++) {
            int p = (wrp << 5) + (it << 2) + t;
            float sig = 0.f;
#pragma unroll
            for (int i = 0; i < 3; i++) {
                float4 A  = s_set[p * 9 + i * 3 + 0];
                float4 W  = s_set[p * 9 + i * 3 + 1];
                float4 Lw = s_set[p * 9 + i * 3 + 2];
                const char* tb = tb0 + (size_t)i * (MAXHW * 128);
                const char* lb = lb0 + (size_t)i * (MAXG * 128);
                int b00 = __float_as_int(A.x);
                int dx  = __float_as_int(A.y);
                int dy  = __float_as_int(A.z);
                int t0  = __float_as_int(A.w);
                int dt  = __float_as_int(Lw.z);
                float v00 = *(const float*)(tb + b00);
                float v01 = *(const float*)(tb + b00 + dx);
                float v10 = *(const float*)(tb + b00 + dy);
                float v11 = *(const float*)(tb + b00 + dx + dy);
                float l0  = *(const float*)(lb + t0);
                float l1  = *(const float*)(lb + t0 + dt);
                float f = v00 * W.x + v01 * W.y + v10 * W.z + v11 * W.w;
                sig += f * (l0 * Lw.x + l1 * Lw.y);   // denw folded into line
            }
            sig += __shfl_xor_sync(0xffffffffu, sig, 1);
            sig += __shfl_xor_sync(0xffffffffu, sig, 2);
            sig += __shfl_xor_sync(0xffffffffu, sig, 4);
            if (ch == 0) s_sig[p] = sig;
        }
    }
    __syncthreads();

    // ---------- Phase B: alpha + transmittance scan -> weights ----------
    {
        float sfeat = s_sig[tid] - 10.0f;
        float sigma = (sfeat > 15.0f) ? sfeat : log1pf(expf(sfeat));
        float dist  = (tid < Ns - 1) ? (s_z[tid + 1] - s_z[tid])
                                     : (s_z[Ns - 1] - s_z[Ns - 2]);
        float alpha = -expm1f(-sigma * (dist * 25.0f));
        s_A[tid] = 1.0f - alpha + 1e-10f;
        __syncthreads();
        float* cur = s_A;
        float* nxt = s_B;
        for (int off = 1; off < Ns; off <<= 1) {
            float v = cur[tid];
            if (tid >= off) v *= cur[tid - off];
            nxt[tid] = v;
            __syncthreads();
            float* tmp = cur; cur = nxt; nxt = tmp;
        }
        float T = (tid == 0) ? 1.0f : cur[tid - 1];
        s_w[tid] = alpha * T;
    }
    __syncthreads();

    // ---------- Pass C: appearance (lane = channel, 1 pt/iter) ----------
    float acc0 = 0.f, acc1 = 0.f, acc2 = 0.f;
    {
        const char* tb0 = (const char*)g_tex  + (size_t)(8 + lane) * 4;
        const char* lb0 = (const char*)g_ltex + (size_t)(8 + lane) * 4;
        const int p0 = wrp << 5;
        for (int it = 0; it < 32; it++) {
            int p = p0 + it;
            float wp = s_w[p];
#pragma unroll
            for (int i = 0; i < 3; i++) {
                float4 A  = s_set[p * 9 + i * 3 + 0];
                float4 W  = s_set[p * 9 + i * 3 + 1];
                float4 Lw = s_set[p * 9 + i * 3 + 2];
                const char* tb = tb0 + (size_t)i * (MAXHW * 128);
                const char* lb = lb0 + (size_t)i * (MAXG * 128);
                int b00 = __float_as_int(A.x);
                int dx  = __float_as_int(A.y);
                int dy  = __float_as_int(A.z);
                int t0  = __float_as_int(A.w);
                int dt  = __float_as_int(Lw.z);
                float v00 = *(const float*)(tb + b00);
                float v01 = *(const float*)(tb + b00 + dx);
                float v10 = *(const float*)(tb + b00 + dy);
                float v11 = *(const float*)(tb + b00 + dx + dy);
                float l0  = *(const float*)(lb + t0);
                float l1  = *(const float*)(lb + t0 + dt);
                float f = v00 * W.x + v01 * W.y + v10 * W.z + v11 * W.w;
                float L = l0 * Lw.x + l1 * Lw.y;
                float fl = f * L;
                if (i == 0) acc0 = fmaf(fl, wp, acc0);
                if (i == 1) acc1 = fmaf(fl, wp, acc1);
                if (i == 2) acc2 = fmaf(fl, wp, acc2);
            }
        }
    }
    __syncthreads();   // all warps done reading s_set -> safe to reuse

    float* s_feat = (float*)s_set;      // 8 warps x 72 features
    if (lane < 24) {
        s_feat[wrp * 72 +  0 + lane] = acc0;
        s_feat[wrp * 72 + 24 + lane] = acc1;
        s_feat[wrp * 72 + 48 + lane] = acc2;
    }
    __syncthreads();
    if (tid < 72) {
        float F = 0.f;
#pragma unroll
        for (int w = 0; w < 8; w++) F += s_feat[w * 72 + tid];
        s_F[tid] = F;
    }
    __syncthreads();
    if (tid < 3) {
        float q = 0.f;
        for (int j = 0; j < 72; j++) q += s_appw[tid * 72 + j] * s_F[j];
        out[r * 3 + tid] = q;
    }
}

extern "C" void kernel_launch(void* const* d_in, const int* in_sizes, int n_in,
                              void* d_out, int out_size) {
    const float* xyz   = (const float*)d_in[0];
    const float* zvals = (const float*)d_in[2];
    const float* dp    = (const float*)d_in[3];
    const float* dl    = (const float*)d_in[4];
    const float* ap    = (const float*)d_in[5];
    const float* al    = (const float*)d_in[6];
    const float* denw  = (const float*)d_in[7];
    const float* appw  = (const float*)d_in[8];
    const float* aabb  = (const float*)d_in[9];

    int Nr = in_sizes[1] / 3;
    int Ns = in_sizes[2] / Nr;
    int G  = in_sizes[4] / 24;
    int HW = G * G;

    int ntp = (HW + 127) / 128;
    int ntl = (G + 127) / 128;
    prep_kernel<<<3 * ntp + 3 * ntl, 256>>>(dp, ap, dl, al, denw, G);
    render_kernel<<<Nr, Ns>>>(xyz, zvals, appw, aabb, (float*)d_out, Ns, G);
}

// round 6
// speedup vs baseline: 1.6684x; 1.6684x over previous
#include <cuda_runtime.h>

// ---------------------------------------------------------------------------
// TensoRF slim renderer, v6 — single sampling pass, corrected reduction.
//  prep: combined 128B texels g_tex[i][HW][32ch] (ch0-7 density, basis
//        weights folded into the LINE texture; ch8-31 appearance).
//  render (block=ray, 256 thr, warp = 32 consecutive samples):
//    lane = corner*8 + slot. Per point/plane: 1 LDG.128 per corner texel
//    (whole 32-ch texel read across the warp), both line taps broadcast.
//    c4 = wc*(tex .* L) -> corner-reduce (xor8,16) -> each corner GROUP
//    becomes an output row: groups 0-2 dot with appw rows, group 3 with
//    ones on density slots (sigma). Group reduce (xor1,2,4), 1 STS/pt.
//    Then alpha(-expm1) + smem product scan -> weights -> rgb reduce.
// ---------------------------------------------------------------------------

#define MAXG  320
#define MAXHW (MAXG * MAXG)

__device__ float4 g_tex[3ull * MAXHW * 8];   // [i][p][8 float4] texel = 128B
__device__ float4 g_ltex[3 * MAXG * 8];      // [i][g][8 float4]

// ---------------- prep: interleave channels into 128B texels ----------------
__global__ void prep_kernel(const float* __restrict__ dp, const float* __restrict__ ap,
                            const float* __restrict__ dl, const float* __restrict__ al,
                            const float* __restrict__ denw, int G) {
    __shared__ float tile[32][129];
    int HW  = G * G;
    int ntp = (HW + 127) >> 7;
    int ntl = (G + 127) >> 7;
    int b = blockIdx.x;
    if (b < 3 * ntp) {
        int i = b / ntp, t = b - i * ntp;
        int p0 = t << 7;
        int np = min(128, HW - p0);
        for (int idx = threadIdx.x; idx < 32 * 128; idx += blockDim.x) {
            int ch = idx >> 7, p = idx & 127;
            float v = 0.f;
            if (p < np)
                v = (ch < 8) ? dp[(size_t)(i * 8 + ch) * HW + p0 + p]
                             : ap[(size_t)(i * 24 + ch - 8) * HW + p0 + p];
            tile[ch][p] = v;
        }
        __syncthreads();
        float* dst = (float*)(g_tex + ((size_t)i * MAXHW + p0) * 8);
        for (int idx = threadIdx.x; idx < np * 32; idx += blockDim.x) {
            int p = idx >> 5, ch = idx & 31;
            dst[idx] = tile[ch][p];
        }
    } else {
        b -= 3 * ntp;
        int i = b / ntl, t = b - i * ntl;
        int g0 = t << 7;
        int ng = min(128, G - g0);
        for (int idx = threadIdx.x; idx < 32 * 128; idx += blockDim.x) {
            int ch = idx >> 7, g = idx & 127;
            float v = 0.f;
            if (g < ng) {
                if (ch < 8) v = dl[(i * 8 + ch) * G + g0 + g] * denw[i * 8 + ch];
                else        v = al[(i * 24 + ch - 8) * G + g0 + g];
            }
            tile[ch][g] = v;
        }
        __syncthreads();
        float* dst = (float*)(g_ltex + ((size_t)i * MAXG + g0) * 8);
        for (int idx = threadIdx.x; idx < ng * 32; idx += blockDim.x) {
            int g = idx >> 5, ch = idx & 31;
            dst[idx] = tile[ch][g];
        }
    }
}

// ---------------- render ----------------
struct S1D { int i0, i1; float w; };

__device__ __forceinline__ S1D samp1d(float c, int G) {
    float f  = (c + 1.0f) * 0.5f * (float)(G - 1);
    float ff = floorf(f);
    S1D r;
    r.w = f - ff;                 // frac from UNclipped floor (matches ref)
    int i0 = (int)ff;
    i0 = min(max(i0, 0), G - 1);
    r.i0 = i0;
    r.i1 = min(i0 + 1, G - 1);
    return r;
}

__global__ __launch_bounds__(256)
void render_kernel(const float* __restrict__ xyz,
                   const float* __restrict__ zvals,
                   const float* __restrict__ appw,
                   const float* __restrict__ aabb,
                   float* __restrict__ out,
                   int Ns, int G) {
    __shared__ float4 s_set[256 * 6];   // per-pt per-plane: 2 f4 (24KB)
    __shared__ float  s_out[256 * 4];   // q0,q1,q2,sigma per point
    __shared__ float  s_z[256];
    __shared__ float  s_A[256];
    __shared__ float  s_B[256];
    __shared__ float  s_part[24];

    const int r      = blockIdx.x;
    const int tid    = threadIdx.x;
    const int lane   = tid & 31;
    const int wrp    = tid >> 5;
    const int corner = lane >> 3;       // 0..3 (also: output-row group)
    const int slot   = lane & 7;        // 0..7 (f4 index within texel)
    const bool pc1   = (corner & 1) != 0;
    const bool pc2   = (corner & 2) != 0;

    // per-lane OUTPUT weights: group 0-2 -> appw row `corner` on app slots;
    // group 3 -> ones on density slots (sigma; denw folded into line texture).
    float4 Wsel[3];
#pragma unroll
    for (int i = 0; i < 3; i++) {
        if (corner == 3) {
            Wsel[i] = (slot < 2) ? make_float4(1.f, 1.f, 1.f, 1.f)
                                 : make_float4(0.f, 0.f, 0.f, 0.f);
        } else {
            Wsel[i] = (slot >= 2)
                ? *(const float4*)(appw + corner * 72 + i * 24 + (slot - 2) * 4)
                : make_float4(0.f, 0.f, 0.f, 0.f);
        }
    }

    // ---------- setup: per-point sampling data ----------
    {
        size_t base = ((size_t)r * Ns + tid) * 3;
        float nc[3];
#pragma unroll
        for (int k = 0; k < 3; k++) {
            float lo = aabb[k], hi = aabb[3 + k];
            nc[k] = (xyz[base + k] - lo) * (2.0f / (hi - lo)) - 1.0f;
        }
        s_z[tid] = zvals[(size_t)r * Ns + tid];

        const int MA[3] = {0, 0, 1}, MB[3] = {1, 2, 2}, MV[3] = {2, 1, 0};
#pragma unroll
        for (int i = 0; i < 3; i++) {
            S1D sx = samp1d(nc[MA[i]], G);
            S1D sy = samp1d(nc[MB[i]], G);
            S1D st = samp1d(nc[MV[i]], G);
            int b00 = (sy.i0 * G + sx.i0) * 128;
            int dx  = (sx.i1 - sx.i0) * 128;
            int dy  = (sy.i1 - sy.i0) * G * 128;
            int t0  = st.i0 * 128;
            int dt  = (st.i1 - st.i0) * 128;
            s_set[tid * 6 + i * 2 + 0] = make_float4(
                __int_as_float(b00), __int_as_float(dx),
                __int_as_float(dy),  __int_as_float(t0));
            s_set[tid * 6 + i * 2 + 1] = make_float4(
                __int_as_float(dt), sx.w, sy.w, st.w);
        }
    }
    __syncthreads();

    const char* tb0 = (const char*)g_tex  + slot * 16;
    const char* lb0 = (const char*)g_ltex + slot * 16;

    // ---------- main pass: 32 points per warp ----------
    const int p0 = wrp << 5;
    for (int it = 0; it < 32; it++) {
        int p = p0 + it;
        float4 c4[3];
#pragma unroll
        for (int i = 0; i < 3; i++) {
            float4 A = s_set[p * 6 + i * 2 + 0];
            float4 B = s_set[p * 6 + i * 2 + 1];
            int b00 = __float_as_int(A.x);
            int dx  = __float_as_int(A.y);
            int dy  = __float_as_int(A.z);
            int t0  = __float_as_int(A.w);
            int dt  = __float_as_int(B.x);
            float sxw = B.y, syw = B.z, stw = B.w;

            const char* tb = tb0 + (size_t)i * (MAXHW * 128);
            const char* lb = lb0 + (size_t)i * (MAXG * 128);
            int off = b00 + (pc1 ? dx : 0) + (pc2 ? dy : 0);
            float4 tex = __ldg((const float4*)(tb + off));
            float4 l0  = __ldg((const float4*)(lb + t0));
            float4 l1  = __ldg((const float4*)(lb + t0 + dt));

            float lw0 = 1.f - stw;
            float wc  = (pc1 ? sxw : 1.f - sxw) * (pc2 ? syw : 1.f - syw);

            c4[i].x = wc * tex.x * (l0.x * lw0 + l1.x * stw);
            c4[i].y = wc * tex.y * (l0.y * lw0 + l1.y * stw);
            c4[i].z = wc * tex.z * (l0.z * lw0 + l1.z * stw);
            c4[i].w = wc * tex.w * (l0.w * lw0 + l1.w * stw);
        }

        // corner-reduce: sum c4 across the 4 corner groups (lane bits 3,4)
#pragma unroll
        for (int i = 0; i < 3; i++) {
#pragma unroll
            for (int m = 8; m <= 16; m <<= 1) {
                c4[i].x += __shfl_xor_sync(0xffffffffu, c4[i].x, m);
                c4[i].y += __shfl_xor_sync(0xffffffffu, c4[i].y, m);
                c4[i].z += __shfl_xor_sync(0xffffffffu, c4[i].z, m);
                c4[i].w += __shfl_xor_sync(0xffffffffu, c4[i].w, m);
            }
        }

        // each group dots the corner-summed features with its output row
        float val = 0.f;
#pragma unroll
        for (int i = 0; i < 3; i++) {
            val += c4[i].x * Wsel[i].x + c4[i].y * Wsel[i].y
                 + c4[i].z * Wsel[i].z + c4[i].w * Wsel[i].w;
        }
        val += __shfl_xor_sync(0xffffffffu, val, 1);
        val += __shfl_xor_sync(0xffffffffu, val, 2);
        val += __shfl_xor_sync(0xffffffffu, val, 4);
        if (slot == 0) s_out[p * 4 + corner] = val;
    }
    __syncthreads();

    // ---------- alpha + transmittance scan -> weights ----------
    float w;
    {
        float sfeat = s_out[tid * 4 + 3] - 10.0f;
        float sigma = (sfeat > 15.0f) ? sfeat : log1pf(expf(sfeat));
        float dist  = (tid < Ns - 1) ? (s_z[tid + 1] - s_z[tid])
                                     : (s_z[Ns - 1] - s_z[Ns - 2]);
        float alpha = -expm1f(-sigma * (dist * 25.0f));
        s_A[tid] = 1.0f - alpha + 1e-10f;
        __syncthreads();
        float* cur = s_A;
        float* nxt = s_B;
        for (int off = 1; off < Ns; off <<= 1) {
            float v = cur[tid];
            if (tid >= off) v *= cur[tid - off];
            nxt[tid] = v;
            __syncthreads();
            float* tmp = cur; cur = nxt; nxt = tmp;
        }
        float T = (tid == 0) ? 1.0f : cur[tid - 1];
        w = alpha * T;
    }

    // ---------- weighted rgb sum ----------
    float q0 = w * s_out[tid * 4 + 0];
    float q1 = w * s_out[tid * 4 + 1];
    float q2 = w * s_out[tid * 4 + 2];
#pragma unroll
    for (int m = 16; m > 0; m >>= 1) {
        q0 += __shfl_xor_sync(0xffffffffu, q0, m);
        q1 += __shfl_xor_sync(0xffffffffu, q1, m);
        q2 += __shfl_xor_sync(0xffffffffu, q2, m);
    }
    if (lane == 0) {
        s_part[wrp * 3 + 0] = q0;
        s_part[wrp * 3 + 1] = q1;
        s_part[wrp * 3 + 2] = q2;
    }
    __syncthreads();
    if (tid < 3) {
        float sum = 0.f;
#pragma unroll
        for (int ww = 0; ww < 8; ww++) sum += s_part[ww * 3 + tid];
        out[r * 3 + tid] = sum;
    }
}

extern "C" void kernel_launch(void* const* d_in, const int* in_sizes, int n_in,
                              void* d_out, int out_size) {
    const float* xyz   = (const float*)d_in[0];
    const float* zvals = (const float*)d_in[2];
    const float* dp    = (const float*)d_in[3];
    const float* dl    = (const float*)d_in[4];
    const float* ap    = (const float*)d_in[5];
    const float* al    = (const float*)d_in[6];
    const float* denw  = (const float*)d_in[7];
    const float* appw  = (const float*)d_in[8];
    const float* aabb  = (const float*)d_in[9];

    int Nr = in_sizes[1] / 3;
    int Ns = in_sizes[2] / Nr;
    int G  = in_sizes[4] / 24;
    int HW = G * G;

    int ntp = (HW + 127) / 128;
    int ntl = (G + 127) / 128;
    prep_kernel<<<3 * ntp + 3 * ntl, 256>>>(dp, ap, dl, al, denw, G);
    render_kernel<<<Nr, Ns>>>(xyz, zvals, appw, aabb, (float*)d_out, Ns, G);
}

// round 7
// speedup vs baseline: 1.8081x; 1.0838x over previous
#include <cuda_runtime.h>

// ---------------------------------------------------------------------------
// TensoRF slim renderer, v7 — LSU-minimal single pass.
//  prep: combined 128B texels g_tex[i][HW][32ch] (ch0-7 density, basis
//        weights folded into the LINE texture; ch8-31 appearance).
//  render (block=ray, 256 thr, warp = 32 samples):
//    lane = corner*8 + slot. Per point/plane: 1 LDG.128 per corner texel +
//    2 tap LDGs (1 line each). Per-lane 4-row partials with appw rows in
//    registers; 6-shuffle multi-output butterfly reduce -> (q0,q1,q2,sigma).
//    Per-plane sampling record packed into ONE float4 (step bits in the low
//    bits of 128B-aligned offsets) + one stw float4 per point: 4 LDS/pt.
//    Then alpha(-expm1) + smem product scan -> weights -> rgb reduce.
// ---------------------------------------------------------------------------

#define MAXG  320
#define MAXHW (MAXG * MAXG)

__device__ float4 g_tex[3ull * MAXHW * 8];   // [i][p][8 float4] texel = 128B
__device__ float4 g_ltex[3 * MAXG * 8];      // [i][g][8 float4]

// ---------------- prep: interleave channels into 128B texels ----------------
__global__ void prep_kernel(const float* __restrict__ dp, const float* __restrict__ ap,
                            const float* __restrict__ dl, const float* __restrict__ al,
                            const float* __restrict__ denw, int G) {
    __shared__ float tile[32][129];
    int HW  = G * G;
    int ntp = (HW + 127) >> 7;
    int ntl = (G + 127) >> 7;
    int b = blockIdx.x;
    if (b < 3 * ntp) {
        int i = b / ntp, t = b - i * ntp;
        int p0 = t << 7;
        int np = min(128, HW - p0);
        for (int idx = threadIdx.x; idx < 32 * 128; idx += blockDim.x) {
            int ch = idx >> 7, p = idx & 127;
            float v = 0.f;
            if (p < np)
                v = (ch < 8) ? dp[(size_t)(i * 8 + ch) * HW + p0 + p]
                             : ap[(size_t)(i * 24 + ch - 8) * HW + p0 + p];
            tile[ch][p] = v;
        }
        __syncthreads();
        float* dst = (float*)(g_tex + ((size_t)i * MAXHW + p0) * 8);
        for (int idx = threadIdx.x; idx < np * 32; idx += blockDim.x) {
            int p = idx >> 5, ch = idx & 31;
            dst[idx] = tile[ch][p];
        }
    } else {
        b -= 3 * ntp;
        int i = b / ntl, t = b - i * ntl;
        int g0 = t << 7;
        int ng = min(128, G - g0);
        for (int idx = threadIdx.x; idx < 32 * 128; idx += blockDim.x) {
            int ch = idx >> 7, g = idx & 127;
            float v = 0.f;
            if (g < ng) {
                if (ch < 8) v = dl[(i * 8 + ch) * G + g0 + g] * denw[i * 8 + ch];
                else        v = al[(i * 24 + ch - 8) * G + g0 + g];
            }
            tile[ch][g] = v;
        }
        __syncthreads();
        float* dst = (float*)(g_ltex + ((size_t)i * MAXG + g0) * 8);
        for (int idx = threadIdx.x; idx < ng * 32; idx += blockDim.x) {
            int g = idx >> 5, ch = idx & 31;
            dst[idx] = tile[ch][g];
        }
    }
}

// ---------------- render ----------------
struct S1D { int i0, i1; float w; };

__device__ __forceinline__ S1D samp1d(float c, int G) {
    float f  = (c + 1.0f) * 0.5f * (float)(G - 1);
    float ff = floorf(f);
    S1D r;
    r.w = f - ff;                 // frac from UNclipped floor (matches ref)
    int i0 = (int)ff;
    i0 = min(max(i0, 0), G - 1);
    r.i0 = i0;
    r.i1 = min(i0 + 1, G - 1);
    return r;
}

__global__ __launch_bounds__(256, 3)
void render_kernel(const float* __restrict__ xyz,
                   const float* __restrict__ zvals,
                   const float* __restrict__ appw,
                   const float* __restrict__ aabb,
                   float* __restrict__ out,
                   int Ns, int G) {
    __shared__ float4 s_setA[256 * 3];  // per-pt per-plane packed record (12KB)
    __shared__ float4 s_setB[256];      // per-pt: stw x3 (4KB)
    __shared__ float  s_out[256 * 4];   // q0,q1,q2,sigma per point
    __shared__ float  s_z[256];
    __shared__ float  s_A[256];
    __shared__ float  s_B[256];
    __shared__ float  s_part[24];

    const int r      = blockIdx.x;
    const int tid    = threadIdx.x;
    const int lane   = tid & 31;
    const int wrp    = tid >> 5;
    const int corner = lane >> 3;       // 0..3
    const int slot   = lane & 7;        // 0..7 (f4 index within texel)
    const bool pc1   = (corner & 1) != 0;
    const bool pc2   = (corner & 2) != 0;
    const bool isApp = (slot >= 2);
    const int  G128  = G * 128;

    // appw rows in registers: W[row][plane] (zeros on density lanes)
    float4 W[3][3];
#pragma unroll
    for (int rr = 0; rr < 3; rr++)
#pragma unroll
        for (int i = 0; i < 3; i++)
            W[rr][i] = isApp
                ? *(const float4*)(appw + rr * 72 + i * 24 + (slot - 2) * 4)
                : make_float4(0.f, 0.f, 0.f, 0.f);

    // ---------- setup: per-point sampling data ----------
    {
        size_t base = ((size_t)r * Ns + tid) * 3;
        float nc[3];
#pragma unroll
        for (int k = 0; k < 3; k++) {
            float lo = aabb[k], hi = aabb[3 + k];
            nc[k] = (xyz[base + k] - lo) * (2.0f / (hi - lo)) - 1.0f;
        }
        s_z[tid] = zvals[(size_t)r * Ns + tid];

        const int MA[3] = {0, 0, 1}, MB[3] = {1, 2, 2}, MV[3] = {2, 1, 0};
        float stw3[3];
#pragma unroll
        for (int i = 0; i < 3; i++) {
            S1D sx = samp1d(nc[MA[i]], G);
            S1D sy = samp1d(nc[MB[i]], G);
            S1D st = samp1d(nc[MV[i]], G);
            // A: texel index <<2 | dyb<<1 | dxb   (byte base = (A>>2)<<7)
            int A = ((sy.i0 * G + sx.i0) << 2)
                  | ((sy.i1 - sy.i0) << 1) | (sx.i1 - sx.i0);
            // B: tap byte offset (mult of 128) | dtb
            int B = (st.i0 << 7) | (st.i1 - st.i0);
            s_setA[tid * 3 + i] = make_float4(
                __int_as_float(A), __int_as_float(B), sx.w, sy.w);
            stw3[i] = st.w;
        }
        s_setB[tid] = make_float4(stw3[0], stw3[1], stw3[2], 0.f);
    }
    __syncthreads();

    const char* tb0 = (const char*)g_tex  + slot * 16;
    const char* lb0 = (const char*)g_ltex + slot * 16;

    // ---------- main pass: 32 points per warp ----------
    const int p0 = wrp << 5;
    for (int it = 0; it < 32; it++) {
        int p = p0 + it;
        float4 SB = s_setB[p];
        float stw3[3] = {SB.x, SB.y, SB.z};

        float v0 = 0.f, v1 = 0.f, v2 = 0.f, fsum = 0.f;
#pragma unroll
        for (int i = 0; i < 3; i++) {
            float4 SA = s_setA[p * 3 + i];
            int A = __float_as_int(SA.x);
            int B = __float_as_int(SA.y);
            float sxw = SA.z, syw = SA.w;

            int base = (A >> 2) << 7;
            int dx   = (A & 1) << 7;
            int dyv  = (A & 2) ? G128 : 0;
            int off  = base + (pc1 ? dx : 0) + (pc2 ? dyv : 0);
            int t    = B & ~1;
            int dt   = (B & 1) << 7;

            const char* tb = tb0 + (size_t)i * (MAXHW * 128);
            const char* lb = lb0 + (size_t)i * (MAXG * 128);
            float4 tex = __ldg((const float4*)(tb + off));
            float4 l0  = __ldg((const float4*)(lb + t));
            float4 l1  = __ldg((const float4*)(lb + t + dt));

            float wc  = (pc1 ? sxw : 1.f - sxw) * (pc2 ? syw : 1.f - syw);
            float stw = stw3[i];
            float s1  = wc * stw;        // fold wc into the tap lerp
            float s0  = wc - s1;

            float4 g;
            g.x = tex.x * (l0.x * s0 + l1.x * s1);
            g.y = tex.y * (l0.y * s0 + l1.y * s1);
            g.z = tex.z * (l0.z * s0 + l1.z * s1);
            g.w = tex.w * (l0.w * s0 + l1.w * s1);

            v0 += g.x * W[0][i].x + g.y * W[0][i].y + g.z * W[0][i].z + g.w * W[0][i].w;
            v1 += g.x * W[1][i].x + g.y * W[1][i].y + g.z * W[1][i].z + g.w * W[1][i].w;
            v2 += g.x * W[2][i].x + g.y * W[2][i].y + g.z * W[2][i].z + g.w * W[2][i].w;
            fsum += (g.x + g.y) + (g.z + g.w);
        }
        float v3 = isApp ? 0.f : fsum;   // sigma: density slots only

        // 6-shuffle 4-output butterfly reduce; row r lands on lanes (lane&3)==r
        const int b0 = lane & 1;
        const int b1 = lane & 2;
        float s1v = b0 ? v0 : v1;
        float r1  = __shfl_xor_sync(0xffffffffu, s1v, 1);
        float u0  = (b0 ? v1 : v0) + r1;           // row b0
        float s2v = b0 ? v2 : v3;
        float r2  = __shfl_xor_sync(0xffffffffu, s2v, 1);
        float u1  = (b0 ? v3 : v2) + r2;           // row 2+b0
        float s3v = b1 ? u0 : u1;
        float r3  = __shfl_xor_sync(0xffffffffu, s3v, 2);
        float wv  = (b1 ? u1 : u0) + r3;           // row lane&3
        wv += __shfl_xor_sync(0xffffffffu, wv, 4);
        wv += __shfl_xor_sync(0xffffffffu, wv, 8);
        wv += __shfl_xor_sync(0xffffffffu, wv, 16);
        if (lane < 4) s_out[p * 4 + lane] = wv;
    }
    __syncthreads();

    // ---------- alpha + transmittance scan -> weights ----------
    float w;
    {
        float sfeat = s_out[tid * 4 + 3] - 10.0f;
        float sigma = (sfeat > 15.0f) ? sfeat : log1pf(expf(sfeat));
        float dist  = (tid < Ns - 1) ? (s_z[tid + 1] - s_z[tid])
                                     : (s_z[Ns - 1] - s_z[Ns - 2]);
        float alpha = -expm1f(-sigma * (dist * 25.0f));
        s_A[tid] = 1.0f - alpha + 1e-10f;
        __syncthreads();
        float* cur = s_A;
        float* nxt = s_B;
        for (int off = 1; off < Ns; off <<= 1) {
            float v = cur[tid];
            if (tid >= off) v *= cur[tid - off];
            nxt[tid] = v;
            __syncthreads();
            float* tmp = cur; cur = nxt; nxt = tmp;
        }
        float T = (tid == 0) ? 1.0f : cur[tid - 1];
        w = alpha * T;
    }

    // ---------- weighted rgb sum ----------
    float q0 = w * s_out[tid * 4 + 0];
    float q1 = w * s_out[tid * 4 + 1];
    float q2 = w * s_out[tid * 4 + 2];
#pragma unroll
    for (int m = 16; m > 0; m >>= 1) {
        q0 += __shfl_xor_sync(0xffffffffu, q0, m);
        q1 += __shfl_xor_sync(0xffffffffu, q1, m);
        q2 += __shfl_xor_sync(0xffffffffu, q2, m);
    }
    if (lane == 0) {
        s_part[wrp * 3 + 0] = q0;
        s_part[wrp * 3 + 1] = q1;
        s_part[wrp * 3 + 2] = q2;
    }
    __syncthreads();
    if (tid < 3) {
        float sum = 0.f;
#pragma unroll
        for (int ww = 0; ww < 8; ww++) sum += s_part[ww * 3 + tid];
        out[r * 3 + tid] = sum;
    }
}

extern "C" void kernel_launch(void* const* d_in, const int* in_sizes, int n_in,
                              void* d_out, int out_size) {
    const float* xyz   = (const float*)d_in[0];
    const float* zvals = (const float*)d_in[2];
    const float* dp    = (const float*)d_in[3];
    const float* dl    = (const float*)d_in[4];
    const float* ap    = (const float*)d_in[5];
    const float* al    = (const float*)d_in[6];
    const float* denw  = (const float*)d_in[7];
    const float* appw  = (const float*)d_in[8];
    const float* aabb  = (const float*)d_in[9];

    int Nr = in_sizes[1] / 3;
    int Ns = in_sizes[2] / Nr;
    int G  = in_sizes[4] / 24;
    int HW = G * G;

    int ntp = (HW + 127) / 128;
    int ntl = (G + 127) / 128;
    prep_kernel<<<3 * ntp + 3 * ntl, 256>>>(dp, ap, dl, al, denw, G);
    render_kernel<<<Nr, Ns>>>(xyz, zvals, appw, aabb, (float*)d_out, Ns, G);
}

// round 8
// speedup vs baseline: 1.9716x; 1.0904x over previous
#include <cuda_runtime.h>

// ---------------------------------------------------------------------------
// TensoRF slim renderer, v8 — packed f32x2 math + flat-index addressing.
//  prep: combined 128B texels g_tex[i][HW][32ch] (ch0-7 density, basis
//        weights folded into the LINE texture; ch8-31 appearance).
//  render (block=ray, 256 thr, warp = 32 samples):
//    lane = corner*8 + slot. Per point/plane: 1 LDG.128 corner texel +
//    2 tap LDGs, addressed as base[idx] (single IMAD.WIDE each; plane
//    offset folded into the stored index). All channel math in packed
//    fp32x2 (FFMA2/FMUL2): tap lerp, tex*L, 4 output-row dots (row 3 =
//    sigma via ones-on-density weights). 6-shuffle butterfly reduce.
//    Then alpha(-expm1) + smem product scan -> weights -> rgb reduce.
// ---------------------------------------------------------------------------

#define MAXG  320
#define MAXHW (MAXG * MAXG)

__device__ float4 g_tex[3ull * MAXHW * 8];   // [i][p][8 float4] texel = 128B
__device__ float4 g_ltex[3 * MAXG * 8];      // [i][g][8 float4]

typedef unsigned long long ull;

__device__ __forceinline__ ull f2pk(float a, float b) {
    ull r; asm("mov.b64 %0,{%1,%2};" : "=l"(r) : "f"(a), "f"(b)); return r;
}
__device__ __forceinline__ float2 f2un(ull v) {
    float2 r; asm("mov.b64 {%0,%1},%2;" : "=f"(r.x), "=f"(r.y) : "l"(v)); return r;
}
__device__ __forceinline__ ull fma2(ull a, ull b, ull c) {
    ull r; asm("fma.rn.f32x2 %0,%1,%2,%3;" : "=l"(r) : "l"(a), "l"(b), "l"(c)); return r;
}
__device__ __forceinline__ ull mul2(ull a, ull b) {
    ull r; asm("mul.rn.f32x2 %0,%1,%2;" : "=l"(r) : "l"(a), "l"(b)); return r;
}

// ---------------- prep: interleave channels into 128B texels ----------------
__global__ void prep_kernel(const float* __restrict__ dp, const float* __restrict__ ap,
                            const float* __restrict__ dl, const float* __restrict__ al,
                            const float* __restrict__ denw, int G) {
    __shared__ float tile[32][129];
    int HW  = G * G;
    int ntp = (HW + 127) >> 7;
    int ntl = (G + 127) >> 7;
    int b = blockIdx.x;
    if (b < 3 * ntp) {
        int i = b / ntp, t = b - i * ntp;
        int p0 = t << 7;
        int np = min(128, HW - p0);
        for (int idx = threadIdx.x; idx < 32 * 128; idx += blockDim.x) {
            int ch = idx >> 7, p = idx & 127;
            float v = 0.f;
            if (p < np)
                v = (ch < 8) ? dp[(size_t)(i * 8 + ch) * HW + p0 + p]
                             : ap[(size_t)(i * 24 + ch - 8) * HW + p0 + p];
            tile[ch][p] = v;
        }
        __syncthreads();
        float* dst = (float*)(g_tex + ((size_t)i * MAXHW + p0) * 8);
        for (int idx = threadIdx.x; idx < np * 32; idx += blockDim.x) {
            int p = idx >> 5, ch = idx & 31;
            dst[idx] = tile[ch][p];
        }
    } else {
        b -= 3 * ntp;
        int i = b / ntl, t = b - i * ntl;
        int g0 = t << 7;
        int ng = min(128, G - g0);
        for (int idx = threadIdx.x; idx < 32 * 128; idx += blockDim.x) {
            int ch = idx >> 7, g = idx & 127;
            float v = 0.f;
            if (g < ng) {
                if (ch < 8) v = dl[(i * 8 + ch) * G + g0 + g] * denw[i * 8 + ch];
                else        v = al[(i * 24 + ch - 8) * G + g0 + g];
            }
            tile[ch][g] = v;
        }
        __syncthreads();
        float* dst = (float*)(g_ltex + ((size_t)i * MAXG + g0) * 8);
        for (int idx = threadIdx.x; idx < ng * 32; idx += blockDim.x) {
            int g = idx >> 5, ch = idx & 31;
            dst[idx] = tile[ch][g];
        }
    }
}

// ---------------- render ----------------
struct S1D { int i0, i1; float w; };

__device__ __forceinline__ S1D samp1d(float c, int G) {
    float f  = (c + 1.0f) * 0.5f * (float)(G - 1);
    float ff = floorf(f);
    S1D r;
    r.w = f - ff;                 // frac from UNclipped floor (matches ref)
    int i0 = (int)ff;
    i0 = min(max(i0, 0), G - 1);
    r.i0 = i0;
    r.i1 = min(i0 + 1, G - 1);
    return r;
}

__global__ __launch_bounds__(256, 3)
void render_kernel(const float* __restrict__ xyz,
                   const float* __restrict__ zvals,
                   const float* __restrict__ appw,
                   const float* __restrict__ aabb,
                   float* __restrict__ out,
                   int Ns, int G) {
    __shared__ float4 s_setA[256 * 3];  // per-pt per-plane (A, T, sxw, syw)
    __shared__ float4 s_setB[256];      // per-pt: stw x3
    __shared__ float  s_out[256 * 4];   // q0,q1,q2,sigma per point
    __shared__ float  s_z[256];
    __shared__ float  s_A[256];
    __shared__ float  s_B[256];
    __shared__ float  s_part[24];

    const int r      = blockIdx.x;
    const int tid    = threadIdx.x;
    const int lane   = tid & 31;
    const int wrp    = tid >> 5;
    const int corner = lane >> 3;       // 0..3
    const int slot   = lane & 7;        // 0..7 (f4 index within texel)
    const bool pc1   = (corner & 1) != 0;
    const bool pc2   = (corner & 2) != 0;
    const bool isApp = (slot >= 2);
    const int  G8    = G * 8;           // y-step in f4 units

    // packed weights: rows 0-2 = appw (zeros on density lanes);
    // row 3 = sigma row: ones on density lanes, zeros on app lanes.
    ull WA[4][3], WB[4][3];
    {
        const ull ones = f2pk(1.f, 1.f);
#pragma unroll
        for (int rr = 0; rr < 3; rr++)
#pragma unroll
            for (int i = 0; i < 3; i++) {
                if (isApp) {
                    float4 w = *(const float4*)(appw + rr * 72 + i * 24 + (slot - 2) * 4);
                    WA[rr][i] = f2pk(w.x, w.y);
                    WB[rr][i] = f2pk(w.z, w.w);
                } else {
                    WA[rr][i] = 0ull; WB[rr][i] = 0ull;
                }
            }
#pragma unroll
        for (int i = 0; i < 3; i++) {
            WA[3][i] = isApp ? 0ull : ones;
            WB[3][i] = isApp ? 0ull : ones;
        }
    }

    // ---------- setup: per-point sampling data ----------
    {
        size_t base = ((size_t)r * Ns + tid) * 3;
        float nc[3];
#pragma unroll
        for (int k = 0; k < 3; k++) {
            float lo = aabb[k], hi = aabb[3 + k];
            nc[k] = (xyz[base + k] - lo) * (2.0f / (hi - lo)) - 1.0f;
        }
        s_z[tid] = zvals[(size_t)r * Ns + tid];

        const int MA[3] = {0, 0, 1}, MB[3] = {1, 2, 2}, MV[3] = {2, 1, 0};
        float stw3[3];
#pragma unroll
        for (int i = 0; i < 3; i++) {
            S1D sx = samp1d(nc[MA[i]], G);
            S1D sy = samp1d(nc[MB[i]], G);
            S1D st = samp1d(nc[MV[i]], G);
            // u00: f4-unit index incl. plane base; A = u00<<2 | dyb<<1 | dxb
            int u00 = i * (MAXHW * 8) + (sy.i0 * G + sx.i0) * 8;
            int A = (u00 << 2) | ((sy.i1 - sy.i0) << 1) | (sx.i1 - sx.i0);
            // taps: f4-unit indices incl. plane base, 16-bit each
            int t0u = i * (MAXG * 8) + st.i0 * 8;
            int t1u = i * (MAXG * 8) + st.i1 * 8;
            int T = t0u | (t1u << 16);
            s_setA[tid * 3 + i] = make_float4(
                __int_as_float(A), __int_as_float(T), sx.w, sy.w);
            stw3[i] = st.w;
        }
        s_setB[tid] = make_float4(stw3[0], stw3[1], stw3[2], 0.f);
    }
    __syncthreads();

    const ulonglong2* tbp = (const ulonglong2*)g_tex  + slot;   // stride 8/texel
    const ulonglong2* lbp = (const ulonglong2*)g_ltex + slot;

    // ---------- main pass: 32 points per warp ----------
    const int p0 = wrp << 5;
    for (int it = 0; it < 32; it++) {
        int p = p0 + it;
        float4 SB = s_setB[p];
        float stw3[3] = {SB.x, SB.y, SB.z};

        ull acc[4] = {0ull, 0ull, 0ull, 0ull};
#pragma unroll
        for (int i = 0; i < 3; i++) {
            float4 SA = s_setA[p * 3 + i];
            int A = __float_as_int(SA.x);
            int T = __float_as_int(SA.y);
            float sxw = SA.z, syw = SA.w;

            int u    = (unsigned)A >> 2;
            int ux   = (A & 1) << 3;
            int uyv  = (A & 2) ? G8 : 0;
            int offu = u + (pc1 ? ux : 0) + (pc2 ? uyv : 0);
            int t0u  = T & 0xFFFF;
            int t1u  = (unsigned)T >> 16;

            ulonglong2 tex = __ldg(tbp + offu);
            ulonglong2 l0  = __ldg(lbp + t0u);
            ulonglong2 l1  = __ldg(lbp + t1u);

            float wc = (pc1 ? sxw : 1.f - sxw) * (pc2 ? syw : 1.f - syw);
            float s1 = wc * stw3[i];
            float s0 = wc - s1;
            ull s0p = f2pk(s0, s0);
            ull s1p = f2pk(s1, s1);

            ull gA = mul2(tex.x, fma2(l1.x, s1p, mul2(l0.x, s0p)));
            ull gB = mul2(tex.y, fma2(l1.y, s1p, mul2(l0.y, s0p)));
#pragma unroll
            for (int rr = 0; rr < 4; rr++) {
                acc[rr] = fma2(gA, WA[rr][i], acc[rr]);
                acc[rr] = fma2(gB, WB[rr][i], acc[rr]);
            }
        }
        float2 a0 = f2un(acc[0]);
        float2 a1 = f2un(acc[1]);
        float2 a2 = f2un(acc[2]);
        float2 a3 = f2un(acc[3]);
        float v0 = a0.x + a0.y;
        float v1 = a1.x + a1.y;
        float v2 = a2.x + a2.y;
        float v3 = a3.x + a3.y;

        // 6-shuffle 4-output butterfly reduce; row r lands on lanes (lane&3)==r
        const int b0 = lane & 1;
        const int b1 = lane & 2;
        float s1v = b0 ? v0 : v1;
        float r1  = __shfl_xor_sync(0xffffffffu, s1v, 1);
        float u0  = (b0 ? v1 : v0) + r1;           // row b0
        float s2v = b0 ? v2 : v3;
        float r2  = __shfl_xor_sync(0xffffffffu, s2v, 1);
        float u1  = (b0 ? v3 : v2) + r2;           // row 2+b0
        float s3v = b1 ? u0 : u1;
        float r3  = __shfl_xor_sync(0xffffffffu, s3v, 2);
        float wv  = (b1 ? u1 : u0) + r3;           // row lane&3
        wv += __shfl_xor_sync(0xffffffffu, wv, 4);
        wv += __shfl_xor_sync(0xffffffffu, wv, 8);
        wv += __shfl_xor_sync(0xffffffffu, wv, 16);
        if (lane < 4) s_out[p * 4 + lane] = wv;
    }
    __syncthreads();

    // ---------- alpha + transmittance scan -> weights ----------
    float w;
    {
        float sfeat = s_out[tid * 4 + 3] - 10.0f;
        float sigma = (sfeat > 15.0f) ? sfeat : log1pf(expf(sfeat));
        float dist  = (tid < Ns - 1) ? (s_z[tid + 1] - s_z[tid])
                                     : (s_z[Ns - 1] - s_z[Ns - 2]);
        float alpha = -expm1f(-sigma * (dist * 25.0f));
        s_A[tid] = 1.0f - alpha + 1e-10f;
        __syncthreads();
        float* cur = s_A;
        float* nxt = s_B;
        for (int off = 1; off < Ns; off <<= 1) {
            float v = cur[tid];
            if (tid >= off) v *= cur[tid - off];
            nxt[tid] = v;
            __syncthreads();
            float* tmp = cur; cur = nxt; nxt = tmp;
        }
        float T = (tid == 0) ? 1.0f : cur[tid - 1];
        w = alpha * T;
    }

    // ---------- weighted rgb sum ----------
    float q0 = w * s_out[tid * 4 + 0];
    float q1 = w * s_out[tid * 4 + 1];
    float q2 = w * s_out[tid * 4 + 2];
#pragma unroll
    for (int m = 16; m > 0; m >>= 1) {
        q0 += __shfl_xor_sync(0xffffffffu, q0, m);
        q1 += __shfl_xor_sync(0xffffffffu, q1, m);
        q2 += __shfl_xor_sync(0xffffffffu, q2, m);
    }
    if (lane == 0) {
        s_part[wrp * 3 + 0] = q0;
        s_part[wrp * 3 + 1] = q1;
        s_part[wrp * 3 + 2] = q2;
    }
    __syncthreads();
    if (tid < 3) {
        float sum = 0.f;
#pragma unroll
        for (int ww = 0; ww < 8; ww++) sum += s_part[ww * 3 + tid];
        out[r * 3 + tid] = sum;
    }
}

extern "C" void kernel_launch(void* const* d_in, const int* in_sizes, int n_in,
                              void* d_out, int out_size) {
    const float* xyz   = (const float*)d_in[0];
    const float* zvals = (const float*)d_in[2];
    const float* dp    = (const float*)d_in[3];
    const float* dl    = (const float*)d_in[4];
    const float* ap    = (const float*)d_in[5];
    const float* al    = (const float*)d_in[6];
    const float* denw  = (const float*)d_in[7];
    const float* appw  = (const float*)d_in[8];
    const float* aabb  = (const float*)d_in[9];

    int Nr = in_sizes[1] / 3;
    int Ns = in_sizes[2] / Nr;
    int G  = in_sizes[4] / 24;
    int HW = G * G;

    int ntp = (HW + 127) / 128;
    int ntl = (G + 127) / 128;
    prep_kernel<<<3 * ntp + 3 * ntl, 256>>>(dp, ap, dl, al, denw, G);
    render_kernel<<<Nr, Ns>>>(xyz, zvals, appw, aabb, (float*)d_out, Ns, G);
}